// round 8
// baseline (speedup 1.0000x reference)
#include <cuda_runtime.h>
#include <cstdint>

#define NUM_C   64
#define FD      128
#define FD4     32          // float4 per feature row
#define BLK     256
#define NWARP   8
#define GRID    888         // 6 blocks per SM (148 SMs)
#define PER_CAP 1152        // max rows per block (ceil(1e6/888)=1127)
#define GRP     4           // rows per batched group
#define N_PAIRS 2016        // 64*63/2

__device__ float        g_sums[NUM_C * FD];
__device__ int          g_counts[NUM_C];
__device__ float        g_sumsq;
__device__ unsigned int g_ticket;

__device__ __forceinline__ void flush_acc(int c, int l, const float4& a) {
    float* gs = &g_sums[c * FD + (l << 2)];
    atomicAdd(gs + 0, a.x); atomicAdd(gs + 1, a.y);
    atomicAdd(gs + 2, a.z); atomicAdd(gs + 3, a.w);
}

__global__ void __launch_bounds__(BLK, 6)
fused_k(const float* __restrict__ feat, const int* __restrict__ tgt, int B,
        float* __restrict__ out)
{
    // 32KB union: phases A-C use scomb/stgt; last-block epilogue reuses it as cent[]
    __shared__ __align__(16) unsigned char u_smem[NUM_C * FD * 4];
    unsigned int*  scomb = (unsigned int*)u_smem;            // [PER_CAP] rowid|class<<16
    unsigned char* stgt  = u_smem + 4 * PER_CAP;             // [PER_CAP]
    float*         cent  = (float*)u_smem;                   // [NUM_C*FD] epilogue alias

    __shared__ int   hist[NUM_C];
    __shared__ int   cur[NUM_C];
    __shared__ float s_red[NWARP], s_sq[NWARP], s_hred[NWARP];
    __shared__ int   s_last;

    const int tid = threadIdx.x;
    const int w = tid >> 5, l = tid & 31;

    const int per = (B + GRID - 1) / GRID;
    const int r0  = blockIdx.x * per;
    int n = B - r0; if (n > per) n = per; if (n < 0) n = 0;

    if (tid < NUM_C) hist[tid] = 0;
    __syncthreads();

    // ---- phase A: load targets, histogram ----
    for (int i = tid; i < n; i += BLK) {
        int t = tgt[r0 + i];
        stgt[i] = (unsigned char)t;
        atomicAdd(&hist[t], 1);
    }
    __syncthreads();

    // ---- exclusive prefix over 64 counts (warp 0) ----
    if (w == 0) {
        int a = hist[l], b = hist[l + 32];
        int ia = a, ib = b;
#pragma unroll
        for (int o = 1; o < 32; o <<= 1) { int t = __shfl_up_sync(0xffffffffu, ia, o); if (l >= o) ia += t; }
#pragma unroll
        for (int o = 1; o < 32; o <<= 1) { int t = __shfl_up_sync(0xffffffffu, ib, o); if (l >= o) ib += t; }
        int totA = __shfl_sync(0xffffffffu, ia, 31);
        cur[l]      = ia - a;
        cur[l + 32] = totA + ib - b;
    }
    __syncthreads();

    // ---- phase B: scatter (rowid | class<<16) into class-sorted order ----
    for (int i = tid; i < n; i += BLK) {
        int t = stgt[i];
        int pos = atomicAdd(&cur[t], 1);
        scomb[pos] = (unsigned int)i | ((unsigned int)t << 16);
    }
    __syncthreads();

    // ---- phase C: contiguous-chunk gather, register accumulate ----
    const float4* fl = (const float4*)feat + l;   // lane offset pre-added
    const int p0 = (n * w) / NWARP;
    const int p1 = (n * (w + 1)) / NWARP;

    float sq0 = 0.f, sq1 = 0.f;
    float4 acc = make_float4(0.f, 0.f, 0.f, 0.f);
    int ccur = (p0 < p1) ? (int)(scomb[p0] >> 16) : 0;

    int p = p0;
    for (; p + GRP <= p1; p += GRP) {
        unsigned int cb[GRP];
#pragma unroll
        for (int u = 0; u < GRP; u++) cb[u] = scomb[p + u];
        float4 v[GRP];
#pragma unroll
        for (int u = 0; u < GRP; u++)
            v[u] = fl[(size_t)(r0 + (cb[u] & 0xffffu)) * FD4];  // unconditional batch
#pragma unroll
        for (int u = 0; u < GRP; u++) {
            float4 x = v[u];
            int c = (int)(cb[u] >> 16);
            if (c != ccur) {                          // warp-uniform, rare
                flush_acc(ccur, l, acc);
                acc = make_float4(0.f, 0.f, 0.f, 0.f);
                ccur = c;
            }
            acc.x += x.x; acc.y += x.y; acc.z += x.z; acc.w += x.w;
            if (u & 1) sq1 = fmaf(x.x, x.x, fmaf(x.y, x.y, fmaf(x.z, x.z, fmaf(x.w, x.w, sq1))));
            else       sq0 = fmaf(x.x, x.x, fmaf(x.y, x.y, fmaf(x.z, x.z, fmaf(x.w, x.w, sq0))));
        }
    }
    for (; p < p1; p++) {
        unsigned int cb = scomb[p];
        int c = (int)(cb >> 16);
        float4 x = fl[(size_t)(r0 + (cb & 0xffffu)) * FD4];
        if (c != ccur) {
            flush_acc(ccur, l, acc);
            acc = make_float4(0.f, 0.f, 0.f, 0.f);
            ccur = c;
        }
        acc.x += x.x; acc.y += x.y; acc.z += x.z; acc.w += x.w;
        sq0 = fmaf(x.x, x.x, fmaf(x.y, x.y, fmaf(x.z, x.z, fmaf(x.w, x.w, sq0))));
    }
    if (p1 > p0) flush_acc(ccur, l, acc);

    // ---- block-level reductions & flush ----
    float sq = sq0 + sq1;
#pragma unroll
    for (int o = 16; o > 0; o >>= 1) sq += __shfl_down_sync(0xffffffffu, sq, o);
    if (l == 0) s_sq[w] = sq;
    if (tid < NUM_C) atomicAdd(&g_counts[tid], hist[tid]);
    __syncthreads();
    if (tid == 0) {
        float t = 0.f;
#pragma unroll
        for (int k = 0; k < NWARP; k++) t += s_sq[k];
        atomicAdd(&g_sumsq, t);
    }

    __threadfence();
    __syncthreads();
    if (tid == 0) {
        unsigned int tk = atomicAdd(&g_ticket, 1u);
        s_last = (tk == gridDim.x - 1);
    }
    __syncthreads();
    if (!s_last) return;

    // ================= last block: epilogue (cent aliases u_smem) =================
    __threadfence();

    float ipart = 0.f;
    for (int i = tid; i < NUM_C * FD; i += BLK) {
        const int c = i >> 7;
        float cntc = fmaxf((float)g_counts[c], 1.0f);
        float s  = g_sums[i];
        float ce = s / cntc;
        cent[i]  = ce;
        ipart   += s * ce;                 // sum_c cnt_c * ||cent_c||^2
        g_sums[i] = 0.f;                   // reset for next graph replay
    }
    float ssq = 0.f;
    if (tid == 0) { ssq = g_sumsq; g_sumsq = 0.f; g_ticket = 0u; }
    __syncthreads();                       // all reads of g_counts done
    if (tid < NUM_C) g_counts[tid] = 0;

#pragma unroll
    for (int o = 16; o > 0; o >>= 1) ipart += __shfl_down_sync(0xffffffffu, ipart, o);
    if (l == 0) s_red[w] = ipart;
    __syncthreads();

    // pairwise hinge: one (i,j) pair per warp iter, lanes cover 128 dims as float4
    const float4* c4 = (const float4*)cent;
    float hsum = 0.f;
    for (int i = w; i < NUM_C - 1; i += NWARP) {
        float4 a = c4[i * FD4 + l];
        for (int j = i + 1; j < NUM_C; j++) {
            float4 b = c4[j * FD4 + l];
            float dx = a.x - b.x, dy = a.y - b.y, dz = a.z - b.z, dw = a.w - b.w;
            float d2 = dx * dx + dy * dy + dz * dz + dw * dw;
#pragma unroll
            for (int o = 16; o > 0; o >>= 1) d2 += __shfl_down_sync(0xffffffffu, d2, o);
            if (l == 0) {
                float wt = (i == 1 && j == 2) ? 2.0f : 1.0f;
                hsum += wt * fmaxf(2.0f - d2, 0.0f);     // MARGIN = 2
            }
        }
    }
    if (l == 0) s_hred[w] = hsum;
    __syncthreads();

    if (tid == 0) {
        float isum = 0.f, hs = 0.f;
#pragma unroll
        for (int k = 0; k < NWARP; k++) { isum += s_red[k]; hs += s_hred[k]; }
        out[0] = (ssq - isum) / (float)B + hs / (float)N_PAIRS;
    }
}

extern "C" void kernel_launch(void* const* d_in, const int* in_sizes, int n_in,
                              void* d_out, int out_size) {
    const float* feat = (const float*)d_in[0];
    const int*   tgt  = (const int*)d_in[1];
    const int B = in_sizes[1];
    fused_k<<<GRID, BLK>>>(feat, tgt, B, (float*)d_out);
}

// round 9
// speedup vs baseline: 1.5732x; 1.5732x over previous
#include <cuda_runtime.h>
#include <cstdint>

#define NUM_C   64
#define FD      128
#define FD4     32          // float4 per feature row
#define BLK     256
#define NWARP   8
#define GRID    592         // 4 blocks per SM (148 SMs)
#define PER_CAP 1792        // max rows per block (ceil(1e6/592)=1690)
#define GRP     4           // rows per batched group
#define CPW     (NUM_C / NWARP)  // classes per warp = 8
#define N_PAIRS 2016        // 64*63/2

__device__ float        g_sums[NUM_C * FD];
__device__ int          g_counts[NUM_C];
__device__ float        g_sumsq;
__device__ unsigned int g_ticket;

__global__ void __launch_bounds__(BLK, 4)
fused_k(const float* __restrict__ feat, const int* __restrict__ tgt, int B,
        float* __restrict__ out)
{
    // 32KB block accumulator (exclusive per-class ownership); aliased as cent[] in epilogue
    __shared__ __align__(16) float sacc[NUM_C * FD];
    __shared__ unsigned int  scomb[PER_CAP];     // sorted: rowid | (class<<16)
    __shared__ unsigned char stgt[PER_CAP];
    __shared__ int   hist[NUM_C];
    __shared__ int   pref[NUM_C];
    __shared__ int   cur[NUM_C];
    __shared__ float s_red[NWARP], s_sq[NWARP], s_hred[NWARP];
    __shared__ int   s_last;

    const int tid = threadIdx.x;
    const int w = tid >> 5, l = tid & 31;

    const int per = (B + GRID - 1) / GRID;
    const int r0  = blockIdx.x * per;
    int n = B - r0; if (n > per) n = per; if (n < 0) n = 0;

    // zero accumulator + histogram
    float4* sacc4 = (float4*)sacc;
    for (int i = tid; i < NUM_C * FD4; i += BLK) sacc4[i] = make_float4(0.f, 0.f, 0.f, 0.f);
    if (tid < NUM_C) hist[tid] = 0;
    __syncthreads();

    // ---- phase A: load targets, histogram ----
    for (int i = tid; i < n; i += BLK) {
        int t = tgt[r0 + i];
        stgt[i] = (unsigned char)t;
        atomicAdd(&hist[t], 1);
    }
    __syncthreads();

    // ---- exclusive prefix over 64 counts (warp 0) ----
    if (w == 0) {
        int a = hist[l], b = hist[l + 32];
        int ia = a, ib = b;
#pragma unroll
        for (int o = 1; o < 32; o <<= 1) { int t = __shfl_up_sync(0xffffffffu, ia, o); if (l >= o) ia += t; }
#pragma unroll
        for (int o = 1; o < 32; o <<= 1) { int t = __shfl_up_sync(0xffffffffu, ib, o); if (l >= o) ib += t; }
        int totA = __shfl_sync(0xffffffffu, ia, 31);
        pref[l]      = ia - a;         cur[l]      = ia - a;
        pref[l + 32] = totA + ib - b;  cur[l + 32] = totA + ib - b;
    }
    __syncthreads();

    // ---- phase B: scatter (rowid | class<<16) into class-sorted order ----
    for (int i = tid; i < n; i += BLK) {
        int t = stgt[i];
        int pos = atomicAdd(&cur[t], 1);
        scomb[pos] = (unsigned int)i | ((unsigned int)t << 16);
    }
    __syncthreads();

    // ---- phase C: warp owns classes [8w, 8w+8); gather + register acc;
    //      flush = ONE plain STS.128 per class (exclusive ownership, no atomics)
    const float4* fl = (const float4*)feat + l;   // lane offset pre-added
    const int p0 = pref[w * CPW];
    const int p1 = (w == NWARP - 1) ? n : pref[w * CPW + CPW];

    float sq0 = 0.f, sq1 = 0.f;
    float4 acc = make_float4(0.f, 0.f, 0.f, 0.f);
    int ccur = (p0 < p1) ? (int)(scomb[p0] >> 16) : -1;

    int p = p0;
    for (; p + GRP <= p1; p += GRP) {
        unsigned int cb[GRP];
#pragma unroll
        for (int u = 0; u < GRP; u++) cb[u] = scomb[p + u];
        float4 v[GRP];
#pragma unroll
        for (int u = 0; u < GRP; u++)
            v[u] = fl[(size_t)(r0 + (cb[u] & 0xffffu)) * FD4];  // unconditional batch
#pragma unroll
        for (int u = 0; u < GRP; u++) {
            float4 x = v[u];
            int c = (int)(cb[u] >> 16);
            if (c != ccur) {                          // warp-uniform, ~8x per warp total
                sacc4[ccur * FD4 + l] = acc;          // plain STS.128
                acc = make_float4(0.f, 0.f, 0.f, 0.f);
                ccur = c;
            }
            acc.x += x.x; acc.y += x.y; acc.z += x.z; acc.w += x.w;
            if (u & 1) sq1 = fmaf(x.x, x.x, fmaf(x.y, x.y, fmaf(x.z, x.z, fmaf(x.w, x.w, sq1))));
            else       sq0 = fmaf(x.x, x.x, fmaf(x.y, x.y, fmaf(x.z, x.z, fmaf(x.w, x.w, sq0))));
        }
    }
    for (; p < p1; p++) {
        unsigned int cb = scomb[p];
        int c = (int)(cb >> 16);
        float4 x = fl[(size_t)(r0 + (cb & 0xffffu)) * FD4];
        if (c != ccur) {
            sacc4[ccur * FD4 + l] = acc;
            acc = make_float4(0.f, 0.f, 0.f, 0.f);
            ccur = c;
        }
        acc.x += x.x; acc.y += x.y; acc.z += x.z; acc.w += x.w;
        sq0 = fmaf(x.x, x.x, fmaf(x.y, x.y, fmaf(x.z, x.z, fmaf(x.w, x.w, sq0))));
    }
    if (p1 > p0) sacc4[ccur * FD4 + l] = acc;         // final run

    __syncthreads();

    // ---- block-end merge: 8192 REDG per block (cheap) ----
    for (int i = tid; i < NUM_C * FD; i += BLK) {
        float s = sacc[i];
        if (s != 0.f) atomicAdd(&g_sums[i], s);
        else          atomicAdd(&g_sums[i], 0.f);     // keep uniform (branchless alt ok)
    }
    if (tid < NUM_C) atomicAdd(&g_counts[tid], hist[tid]);

    float sq = sq0 + sq1;
#pragma unroll
    for (int o = 16; o > 0; o >>= 1) sq += __shfl_down_sync(0xffffffffu, sq, o);
    if (l == 0) s_sq[w] = sq;
    __syncthreads();
    if (tid == 0) {
        float t = 0.f;
#pragma unroll
        for (int k = 0; k < NWARP; k++) t += s_sq[k];
        atomicAdd(&g_sumsq, t);
    }

    __threadfence();
    __syncthreads();
    if (tid == 0) {
        unsigned int tk = atomicAdd(&g_ticket, 1u);
        s_last = (tk == gridDim.x - 1);
    }
    __syncthreads();
    if (!s_last) return;

    // ================= last block: epilogue (cent aliases sacc) =================
    __threadfence();
    float* cent = sacc;

    float ipart = 0.f;
    for (int i = tid; i < NUM_C * FD; i += BLK) {
        const int c = i >> 7;
        float cntc = fmaxf((float)g_counts[c], 1.0f);
        float s  = g_sums[i];
        float ce = s / cntc;
        cent[i]  = ce;
        ipart   += s * ce;                 // sum_c cnt_c * ||cent_c||^2
        g_sums[i] = 0.f;                   // reset for next graph replay
    }
    float ssq = 0.f;
    if (tid == 0) { ssq = g_sumsq; g_sumsq = 0.f; g_ticket = 0u; }
    __syncthreads();                       // all reads of g_counts done
    if (tid < NUM_C) g_counts[tid] = 0;

#pragma unroll
    for (int o = 16; o > 0; o >>= 1) ipart += __shfl_down_sync(0xffffffffu, ipart, o);
    if (l == 0) s_red[w] = ipart;
    __syncthreads();

    // pairwise hinge: one (i,j) pair per warp iter, lanes cover 128 dims as float4
    const float4* c4 = (const float4*)cent;
    float hsum = 0.f;
    for (int i = w; i < NUM_C - 1; i += NWARP) {
        float4 a = c4[i * FD4 + l];
        for (int j = i + 1; j < NUM_C; j++) {
            float4 b = c4[j * FD4 + l];
            float dx = a.x - b.x, dy = a.y - b.y, dz = a.z - b.z, dw = a.w - b.w;
            float d2 = dx * dx + dy * dy + dz * dz + dw * dw;
#pragma unroll
            for (int o = 16; o > 0; o >>= 1) d2 += __shfl_down_sync(0xffffffffu, d2, o);
            if (l == 0) {
                float wt = (i == 1 && j == 2) ? 2.0f : 1.0f;
                hsum += wt * fmaxf(2.0f - d2, 0.0f);     // MARGIN = 2
            }
        }
    }
    if (l == 0) s_hred[w] = hsum;
    __syncthreads();

    if (tid == 0) {
        float isum = 0.f, hs = 0.f;
#pragma unroll
        for (int k = 0; k < NWARP; k++) { isum += s_red[k]; hs += s_hred[k]; }
        out[0] = (ssq - isum) / (float)B + hs / (float)N_PAIRS;
    }
}

extern "C" void kernel_launch(void* const* d_in, const int* in_sizes, int n_in,
                              void* d_out, int out_size) {
    const float* feat = (const float*)d_in[0];
    const int*   tgt  = (const int*)d_in[1];
    const int B = in_sizes[1];
    fused_k<<<GRID, BLK>>>(feat, tgt, B, (float*)d_out);
}